// round 2
// baseline (speedup 1.0000x reference)
#include <cuda_runtime.h>
#include <cuda_bf16.h>
#include <cstdint>
#include <cstddef>

#define NWSEQ 1024
#define TW    64
#define MWORD (NWSEQ*TW)
#define NDOC  32
#define TSENT 32
#define MSENT (NDOC*TSENT)
#define HHID  256
#define HD2   512
#define HD3   768
#define EDIM  200

typedef unsigned long long ull;

// scratch (device globals; allocation-free rule)
__device__ float g_xg [2ull*MWORD*HD3];  // word GRU input gates per dir
__device__ float g_h  [(size_t)MWORD*HD2]; // word BiGRU hidden
__device__ float g_sents[(size_t)MSENT*HD2];
__device__ float g_xg2[2ull*MSENT*HD3];
__device__ float g_h2 [(size_t)MSENT*HD2];

__device__ __forceinline__ ull pk2(float lo, float hi){
    ull r; asm("mov.b64 %0, {%1,%2};" : "=l"(r) : "f"(lo), "f"(hi)); return r;
}
__device__ __forceinline__ float2 upk2(ull v){
    float2 f; asm("mov.b64 {%0,%1}, %2;" : "=f"(f.x), "=f"(f.y) : "l"(v)); return f;
}
// packed f32x2 fma: 2x FFMA throughput on sm_100+
__device__ __forceinline__ ull fma2(ull a, ull b, ull c){
    ull d; asm("fma.rn.f32x2 %0, %1, %2, %3;" : "=l"(d) : "l"(a), "l"(b), "l"(c)); return d;
}
__device__ __forceinline__ float fsig(float x){ return 1.0f/(1.0f + __expf(-x)); }
__device__ __forceinline__ float ftanh(float x){ return 1.0f - 2.0f/(__expf(2.0f*x) + 1.0f); }

// ---------------------------------------------------------------------------
// GEMM: out[dir][m][j] = A[row(m)][:] @ W_dir[:, j] + b_dir[j], j in [0,768)
// row(m) = gather[m] (embedding lookup) or m. 64x64 tiles, BK=8.
// grid: (M/64, 1536/64=24)
// ---------------------------------------------------------------------------
__global__ __launch_bounds__(256) void gemm_xg_kernel(
    const float* __restrict__ A, const int* __restrict__ gather, int K,
    const float* __restrict__ Wf, const float* __restrict__ Wb,
    const float* __restrict__ bf, const float* __restrict__ bb,
    float* __restrict__ out, int M)
{
    __shared__ __align__(16) float sAT[8][68];
    __shared__ __align__(16) float sB [8][64];
    int tid = threadIdx.x;
    int tx = tid & 15, ty = tid >> 4;
    int m0 = blockIdx.x * 64;
    int jg = blockIdx.y * 64;
    int dir = jg / HD3;
    int j0c = jg % HD3;
    const float* W = dir ? Wb : Wf;
    const float* bias = dir ? bb : bf;

    int mA = tid >> 3, kA = tid & 7;
    int r0 = m0 + mA, r1 = r0 + 32;
    const float* ar0 = A + (size_t)(gather ? gather[r0] : r0) * K;
    const float* ar1 = A + (size_t)(gather ? gather[r1] : r1) * K;
    int jB = tid & 63, kB = tid >> 6;

    ull acc[4][2];
#pragma unroll
    for (int r = 0; r < 4; r++){ acc[r][0] = 0ull; acc[r][1] = 0ull; }

    for (int k0 = 0; k0 < K; k0 += 8) {
        __syncthreads();
        sAT[kA][mA]      = ar0[k0 + kA];
        sAT[kA][mA + 32] = ar1[k0 + kA];
        sB[kB][jB]       = W[(size_t)(k0 + kB) * HD3 + j0c + jB];
        sB[kB + 4][jB]   = W[(size_t)(k0 + kB + 4) * HD3 + j0c + jB];
        __syncthreads();
#pragma unroll
        for (int kk = 0; kk < 8; kk++){
            float4 a4 = *(const float4*)&sAT[kk][ty*4];
            float4 b4 = *(const float4*)&sB[kk][tx*4];
            ull b01 = pk2(b4.x, b4.y), b23 = pk2(b4.z, b4.w);
            ull a;
            a = pk2(a4.x, a4.x); acc[0][0]=fma2(a,b01,acc[0][0]); acc[0][1]=fma2(a,b23,acc[0][1]);
            a = pk2(a4.y, a4.y); acc[1][0]=fma2(a,b01,acc[1][0]); acc[1][1]=fma2(a,b23,acc[1][1]);
            a = pk2(a4.z, a4.z); acc[2][0]=fma2(a,b01,acc[2][0]); acc[2][1]=fma2(a,b23,acc[2][1]);
            a = pk2(a4.w, a4.w); acc[3][0]=fma2(a,b01,acc[3][0]); acc[3][1]=fma2(a,b23,acc[3][1]);
        }
    }
    float4 bv = *(const float4*)&bias[j0c + tx*4];
    float* od = out + (size_t)dir * M * HD3;
#pragma unroll
    for (int r = 0; r < 4; r++){
        float2 lo = upk2(acc[r][0]), hi = upk2(acc[r][1]);
        float4 o; o.x = lo.x + bv.x; o.y = lo.y + bv.y; o.z = hi.x + bv.z; o.w = hi.y + bv.w;
        *(float4*)&od[(size_t)(m0 + ty*4 + r) * HD3 + j0c + tx*4] = o;
    }
}

// ---------------------------------------------------------------------------
// GRU scan: persistent per-group blocks, G sequences per block, h in smem.
// Thread j owns hidden unit j (all 3 gates). grid = (NS/G)*2, 256 threads.
// ---------------------------------------------------------------------------
template<int T, int G>
__global__ __launch_bounds__(256) void gru_scan_kernel(
    const float* __restrict__ xg,   // [2][NS*T][768]
    float* __restrict__ hout,       // [NS*T][512]
    const float* __restrict__ Whf, const float* __restrict__ Whb,
    const float* __restrict__ bhf, const float* __restrict__ bhb,
    int NS)
{
    constexpr int P = G / 2;
    __shared__ __align__(16) float sh[256][G];
    int j = threadIdx.x;
    int gpd = NS / G;
    int d = blockIdx.x / gpd;
    int n0 = (blockIdx.x % gpd) * G;
    const float* Wh = d ? Whb : Whf;
    const float* bh = d ? bhb : bhf;
    const float* xgd = xg + (size_t)d * NS * T * HD3;
    float bhr = bh[j], bhz = bh[256 + j], bhn = bh[512 + j];
#pragma unroll
    for (int g = 0; g < G; g++) sh[j][g] = 0.f;
    __syncthreads();

    for (int tt = 0; tt < T; tt++) {
        int t = d ? (T - 1 - tt) : tt;
        float xr[G], xz[G], xn[G];
#pragma unroll
        for (int g = 0; g < G; g++) {
            const float* xp = xgd + ((size_t)(n0 + g) * T + t) * HD3;
            xr[g] = xp[j]; xz[g] = xp[256 + j]; xn[g] = xp[512 + j];
        }
        ull ar[P], az[P], an[P];
#pragma unroll
        for (int p = 0; p < P; p++){
            ar[p] = pk2(bhr, bhr); az[p] = pk2(bhz, bhz); an[p] = pk2(bhn, bhn);
        }
#pragma unroll 4
        for (int k = 0; k < 256; k++) {
            float wr = __ldg(&Wh[(size_t)k*HD3 + j]);
            float wz = __ldg(&Wh[(size_t)k*HD3 + 256 + j]);
            float wn = __ldg(&Wh[(size_t)k*HD3 + 512 + j]);
            ull wr2 = pk2(wr, wr), wz2 = pk2(wz, wz), wn2 = pk2(wn, wn);
#pragma unroll
            for (int p = 0; p < P; p++){
                ull h2 = *(const ull*)&sh[k][2*p];
                ar[p] = fma2(wr2, h2, ar[p]);
                az[p] = fma2(wz2, h2, az[p]);
                an[p] = fma2(wn2, h2, an[p]);
            }
        }
        float hnew[G];
#pragma unroll
        for (int p = 0; p < P; p++){
            float2 fr = upk2(ar[p]), fz = upk2(az[p]), fn = upk2(an[p]);
            int g0 = 2*p, g1 = 2*p + 1;
            {
                float r = fsig(xr[g0] + fr.x), z = fsig(xz[g0] + fz.x);
                float n = ftanh(xn[g0] + r * fn.x);
                hnew[g0] = (1.f - z) * n + z * sh[j][g0];
            }
            {
                float r = fsig(xr[g1] + fr.y), z = fsig(xz[g1] + fz.y);
                float n = ftanh(xn[g1] + r * fn.y);
                hnew[g1] = (1.f - z) * n + z * sh[j][g1];
            }
        }
        __syncthreads();   // all k-loop reads of sh done
#pragma unroll
        for (int g = 0; g < G; g++){
            sh[j][g] = hnew[g];
            hout[((size_t)(n0 + g) * T + t) * HD2 + d * 256 + j] = hnew[g];
        }
        __syncthreads();
    }
}

// ---------------------------------------------------------------------------
// Attention: per-sequence block. GEMM(T x 512 @ 512x512) -> tanh -> ctx dot
// -> sparsemax -> weighted sum of h. FINAL adds doc @ outW + outb.
// ---------------------------------------------------------------------------
template<int T, bool FINAL>
__global__ __launch_bounds__(256) void attn_kernel(
    const float* __restrict__ h,      // [NSEQ*T][512]
    const float* __restrict__ linW,   // [512][512]
    const float* __restrict__ linb,   // [512]
    const float* __restrict__ ctx,    // [512]
    float* __restrict__ outv,         // [nseq][512]  (if !FINAL)
    const float* __restrict__ outW,   // [512][10]    (FINAL)
    const float* __restrict__ outb,   // [10]
    float* __restrict__ outFinal)     // [NDOC][10]
{
    constexpr int R = T / 8;
    __shared__ __align__(16) float sA[T][16];
    __shared__ __align__(16) float sW[16][128];
    __shared__ float sScore[T], sX[T], sSrt[T], sAtt[T];
    __shared__ float sTau, sMax;
    __shared__ float sDoc[512];
    int tid = threadIdx.x;
    int tx = tid & 31, ty = tid >> 5;
    int n = blockIdx.x;
    const float* hbase = h + (size_t)n * T * HD2;

    float partial[R];
#pragma unroll
    for (int r = 0; r < R; r++) partial[r] = 0.f;

    for (int jt = 0; jt < 512; jt += 128) {
        int jj = jt + tx * 4;
        float4 bvv = *(const float4*)&linb[jj];
        ull acc[R][2];
#pragma unroll
        for (int r = 0; r < R; r++){ acc[r][0] = pk2(bvv.x, bvv.y); acc[r][1] = pk2(bvv.z, bvv.w); }

        for (int k0 = 0; k0 < 512; k0 += 16) {
            __syncthreads();
            for (int i = tid; i < T * 16; i += 256) {
                int t = i >> 4, kk = i & 15;
                sA[t][kk] = hbase[(size_t)t * HD2 + k0 + kk];
            }
            for (int i = tid; i < 2048; i += 256) {
                int kk = i >> 7, jw = i & 127;
                sW[kk][jw] = linW[(size_t)(k0 + kk) * HD2 + jt + jw];
            }
            __syncthreads();
#pragma unroll
            for (int kk = 0; kk < 16; kk++){
                float4 b4 = *(const float4*)&sW[kk][tx*4];
                ull b01 = pk2(b4.x, b4.y), b23 = pk2(b4.z, b4.w);
#pragma unroll
                for (int r = 0; r < R; r++){
                    float a = sA[ty * R + r][kk];
                    ull a2 = pk2(a, a);
                    acc[r][0] = fma2(a2, b01, acc[r][0]);
                    acc[r][1] = fma2(a2, b23, acc[r][1]);
                }
            }
        }
        float cx = ctx[jj], cy = ctx[jj+1], cz = ctx[jj+2], cw = ctx[jj+3];
#pragma unroll
        for (int r = 0; r < R; r++){
            float2 lo = upk2(acc[r][0]), hi = upk2(acc[r][1]);
            partial[r] += ftanh(lo.x)*cx + ftanh(lo.y)*cy + ftanh(hi.x)*cz + ftanh(hi.y)*cw;
        }
    }
    // reduce across the 32 lanes (they cover the 512 columns)
#pragma unroll
    for (int r = 0; r < R; r++){
        float v = partial[r];
        for (int o = 16; o; o >>= 1) v += __shfl_xor_sync(0xffffffffu, v, o);
        if (tx == 0) sScore[ty * R + r] = v;
    }
    __syncthreads();

    // sparsemax (exact, Martins & Astudillo)
    if (tid == 0) {
        float mx = sScore[0];
        for (int t = 1; t < T; t++) mx = fmaxf(mx, sScore[t]);
        sMax = mx;
    }
    __syncthreads();
    if (tid < T) {
        float x = sScore[tid] - sMax;
        sX[tid] = x;
        int rank = 0;
        for (int u = 0; u < T; u++){
            float xu = sScore[u] - sMax;
            if (xu > x || (xu == x && u < tid)) rank++;
        }
        sSrt[rank] = x;
    }
    __syncthreads();
    if (tid == 0) {
        float cs = -1.f; int supp = 0; float csAt = 0.f;
        for (int k = 0; k < T; k++){
            cs += sSrt[k];
            if ((float)(k + 1) * sSrt[k] > cs) { supp = k + 1; csAt = cs; }
        }
        sTau = csAt / (float)supp;
    }
    __syncthreads();
    if (tid < T) sAtt[tid] = fmaxf(sX[tid] - sTau, 0.f);
    __syncthreads();

    // weighted sum over timesteps
    for (int j = tid; j < 512; j += 256) {
        float a0 = 0.f;
        for (int t = 0; t < T; t++) a0 += sAtt[t] * hbase[(size_t)t * HD2 + j];
        if (FINAL) sDoc[j] = a0;
        else       outv[(size_t)n * HD2 + j] = a0;
    }
    if (FINAL) {
        __syncthreads();
        if (tid < 10) {
            float s = outb[tid];
            for (int jj2 = 0; jj2 < 512; jj2++) s += sDoc[jj2] * outW[jj2 * 10 + tid];
            outFinal[n * 10 + tid] = s;
        }
    }
}

extern "C" void kernel_launch(void* const* d_in, const int* in_sizes, int n_in,
                              void* d_out, int out_size) {
    const int*   tokens  = (const int*)  d_in[0];
    const float* emb     = (const float*)d_in[1];
    const float* w_Wx_f  = (const float*)d_in[2];
    const float* w_Wh_f  = (const float*)d_in[3];
    const float* w_bx_f  = (const float*)d_in[4];
    const float* w_bh_f  = (const float*)d_in[5];
    const float* w_Wx_b  = (const float*)d_in[6];
    const float* w_Wh_b  = (const float*)d_in[7];
    const float* w_bx_b  = (const float*)d_in[8];
    const float* w_bh_b  = (const float*)d_in[9];
    const float* w_lin_W = (const float*)d_in[10];
    const float* w_lin_b = (const float*)d_in[11];
    const float* w_ctx   = (const float*)d_in[12];
    const float* s_Wx_f  = (const float*)d_in[13];
    const float* s_Wh_f  = (const float*)d_in[14];
    const float* s_bx_f  = (const float*)d_in[15];
    const float* s_bh_f  = (const float*)d_in[16];
    const float* s_Wx_b  = (const float*)d_in[17];
    const float* s_Wh_b  = (const float*)d_in[18];
    const float* s_bx_b  = (const float*)d_in[19];
    const float* s_bh_b  = (const float*)d_in[20];
    const float* s_lin_W = (const float*)d_in[21];
    const float* s_lin_b = (const float*)d_in[22];
    const float* s_ctx   = (const float*)d_in[23];
    const float* out_W   = (const float*)d_in[24];
    const float* out_b   = (const float*)d_in[25];
    float* out = (float*)d_out;

    float *p_xg, *p_h, *p_sents, *p_xg2, *p_h2;
    cudaGetSymbolAddress((void**)&p_xg,   g_xg);
    cudaGetSymbolAddress((void**)&p_h,    g_h);
    cudaGetSymbolAddress((void**)&p_sents,g_sents);
    cudaGetSymbolAddress((void**)&p_xg2,  g_xg2);
    cudaGetSymbolAddress((void**)&p_h2,   g_h2);

    // 1. word-level input gates (embedding gather fused), both dirs
    gemm_xg_kernel<<<dim3(MWORD/64, 24), 256>>>(
        emb, tokens, EDIM, w_Wx_f, w_Wx_b, w_bx_f, w_bx_b, p_xg, MWORD);
    // 2. word BiGRU scan
    gru_scan_kernel<TW, 16><<<(NWSEQ/16)*2, 256>>>(
        p_xg, p_h, w_Wh_f, w_Wh_b, w_bh_f, w_bh_b, NWSEQ);
    // 3. word attention -> sentence vectors
    attn_kernel<TW, false><<<NWSEQ, 256>>>(
        p_h, w_lin_W, w_lin_b, w_ctx, p_sents, nullptr, nullptr, nullptr);
    // 4. sentence-level input gates
    gemm_xg_kernel<<<dim3(MSENT/64, 24), 256>>>(
        p_sents, nullptr, HD2, s_Wx_f, s_Wx_b, s_bx_f, s_bx_b, p_xg2, MSENT);
    // 5. sentence BiGRU scan
    gru_scan_kernel<TSENT, 2><<<(NDOC/2)*2, 256>>>(
        p_xg2, p_h2, s_Wh_f, s_Wh_b, s_bh_f, s_bh_b, NDOC);
    // 6. sentence attention + final classifier
    attn_kernel<TSENT, true><<<NDOC, 256>>>(
        p_h2, s_lin_W, s_lin_b, s_ctx, nullptr, out_W, out_b, out);
}